// round 1
// baseline (speedup 1.0000x reference)
#include <cuda_runtime.h>
#include <cuda_bf16.h>

// Problem constants (from reference_code)
#define NE    1024   // experts (D*D)
#define NB    1024   // batch
#define NH    64     // hidden width
#define ROWS  256    // batch rows per block

// ---------------------------------------------------------------------------
// Main expert kernel: one block = (expert e, tile of 256 batch rows).
// W2[e] is staged in SMEM transposed (Wt[o][j] = W2[e][j][o]) so the inner
// contraction over j is contiguous and every lane broadcasts the same LDS.128.
// Each thread owns one batch row: h[64] lives in registers.
// ---------------------------------------------------------------------------
__global__ __launch_bounds__(ROWS) void golem_expert_kernel(
    const float* __restrict__ noise,   // [E, B, H]
    const float* __restrict__ W2,      // [E, H, H]   (j = input, o = output)
    const float* __restrict__ b2,      // [E, H]
    const float* __restrict__ W3,      // [E, H]
    const float* __restrict__ b3,      // [E]
    float* __restrict__ out)           // [B, E] (B_mat, row-major)
{
    const int e   = blockIdx.x;
    const int tid = threadIdx.x;
    const int b   = blockIdx.y * ROWS + tid;

    __shared__ float Wt[NH][NH + 4];   // +4 pad keeps 16B alignment per row
    __shared__ float s_b2[NH];
    __shared__ float s_W3[NH];

    // Stage W2[e] transposed into shared
    const float* W2e = W2 + (size_t)e * NH * NH;
    for (int i = tid; i < NH * NH; i += ROWS) {
        int j = i >> 6;        // input index
        int o = i & 63;        // output index
        Wt[o][j] = W2e[i];
    }
    if (tid < NH) {
        s_b2[tid] = b2[(size_t)e * NH + tid];
        s_W3[tid] = W3[(size_t)e * NH + tid];
    }
    __syncthreads();

    // h = sigmoid(noise*4 - 2)   (fc1 cancels exactly in the reference)
    float h[NH];
    const float4* nrow =
        (const float4*)(noise + ((size_t)e * NB + (size_t)b) * NH);
    #pragma unroll
    for (int i = 0; i < NH / 4; i++) {
        float4 v = nrow[i];
        float x0 = v.x * 4.0f - 2.0f;
        float x1 = v.y * 4.0f - 2.0f;
        float x2 = v.z * 4.0f - 2.0f;
        float x3 = v.w * 4.0f - 2.0f;
        h[4*i+0] = __fdividef(1.0f, 1.0f + __expf(-x0));
        h[4*i+1] = __fdividef(1.0f, 1.0f + __expf(-x1));
        h[4*i+2] = __fdividef(1.0f, 1.0f + __expf(-x2));
        h[4*i+3] = __fdividef(1.0f, 1.0f + __expf(-x3));
    }

    // fc2 + sigmoid + fc3, one output column at a time
    float acc_out = b3[e];
    #pragma unroll 2
    for (int o = 0; o < NH; o++) {
        float acc = s_b2[o];
        const float4* w = (const float4*)(&Wt[o][0]);
        #pragma unroll
        for (int i = 0; i < NH / 4; i++) {
            float4 wv = w[i];   // broadcast across all lanes (same address)
            acc += h[4*i+0] * wv.x;
            acc += h[4*i+1] * wv.y;
            acc += h[4*i+2] * wv.z;
            acc += h[4*i+3] * wv.w;
        }
        float h2 = __fdividef(1.0f, 1.0f + __expf(-acc));
        acc_out += h2 * s_W3[o];
    }

    // B_mat[b, e]  (transposed vs per-expert layout)
    out[(size_t)b * NE + e] = acc_out;
}

// ---------------------------------------------------------------------------
// T_embed = (1/alpha) * cos(beta*T + bias), appended after B_mat
// ---------------------------------------------------------------------------
__global__ void golem_tembed_kernel(
    const float* __restrict__ T,
    const float* __restrict__ alpha,
    const float* __restrict__ beta,
    const float* __restrict__ bias,
    float* __restrict__ out)
{
    int i = blockIdx.x * blockDim.x + threadIdx.x;
    if (i < NB) {
        float inv_a = __fdividef(1.0f, alpha[0]);
        out[i] = inv_a * cosf(beta[0] * T[i] + bias[0]);
    }
}

// ---------------------------------------------------------------------------
// kernel_launch — inputs per setup_inputs() order:
//  0:T [1024] 1:noise [E*B*H] 2:W1 [E*H] 3:W2 [E*H*H] 4:b2 [E*H]
//  5:W3 [E*H] 6:b3 [E] 7:alpha [1] 8:beta [1] 9:bias [1]
// Output: B_mat [B,E] row-major, then T_embed [B]  (fp32)
// ---------------------------------------------------------------------------
extern "C" void kernel_launch(void* const* d_in, const int* in_sizes, int n_in,
                              void* d_out, int out_size)
{
    const float* T     = (const float*)d_in[0];
    const float* noise = (const float*)d_in[1];
    const float* W2    = (const float*)d_in[3];
    const float* b2    = (const float*)d_in[4];
    const float* W3    = (const float*)d_in[5];
    const float* b3    = (const float*)d_in[6];
    const float* alpha = (const float*)d_in[7];
    const float* beta  = (const float*)d_in[8];
    const float* bias  = (const float*)d_in[9];

    float* out = (float*)d_out;

    dim3 grid(NE, NB / ROWS);
    golem_expert_kernel<<<grid, ROWS>>>(noise, W2, b2, W3, b3, out);

    golem_tembed_kernel<<<4, 256>>>(T, alpha, beta, bias,
                                    out + (size_t)NB * NE);
}

// round 4
// speedup vs baseline: 2.0026x; 2.0026x over previous
#include <cuda_runtime.h>
#include <cuda_fp16.h>
#include <cstdint>

// Problem constants
#define NE       1024   // experts
#define NB       1024   // batch
#define NH       64     // hidden width
#define WARPS    8
#define THREADS  256
#define RPW      128    // rows per warp  (NB / WARPS)
#define CHUNKS   8      // m16 chunks per warp (RPW / 16)
#define LDA      72     // padded halves per SMEM row (144 B -> conflict-free ldmatrix)

struct Smem {
    __half Wt[NH][LDA];          // Wt[o][j] = W2[j][o]  (B, col-major view)
    __half A[WARPS][16][LDA];    // per-warp fp16 h tile
    float  b2s[NH];
    float  W3s[NH];
};

static __device__ __forceinline__ uint32_t smem_u32(const void* p) {
    uint32_t a;
    asm("{ .reg .u64 t; cvta.to.shared.u64 t, %1; cvt.u32.u64 %0, t; }"
        : "=r"(a) : "l"(p));
    return a;
}

static __device__ __forceinline__ float fast_sigmoid(float x) {
    return __fdividef(1.0f, 1.0f + __expf(-x));
}

// h = sigmoid(4u-2) = 0.5 + 0.5*tanh(2u-1): one MUFU.TANH per 2 elements (f16x2)
static __device__ __forceinline__ uint32_t sig2_h(float a, float b) {
    __half2 t = __floats2half2_rn(2.0f * a - 1.0f, 2.0f * b - 1.0f);
    uint32_t ti = *(uint32_t*)&t, to;
    asm("tanh.approx.f16x2 %0, %1;" : "=r"(to) : "r"(ti));
    __half2 th = *(__half2*)&to;
    __half2 hv = __hfma2(th, __half2half2(__float2half(0.5f)),
                             __half2half2(__float2half(0.5f)));
    return *(uint32_t*)&hv;
}

static __device__ __forceinline__ void ldsm_x4(uint32_t* r, uint32_t addr) {
    asm volatile("ldmatrix.sync.aligned.m8n8.x4.shared.b16 {%0,%1,%2,%3}, [%4];"
                 : "=r"(r[0]), "=r"(r[1]), "=r"(r[2]), "=r"(r[3]) : "r"(addr));
}
static __device__ __forceinline__ void ldsm_x2(uint32_t& b0, uint32_t& b1,
                                               uint32_t addr) {
    asm volatile("ldmatrix.sync.aligned.m8n8.x2.shared.b16 {%0,%1}, [%2];"
                 : "=r"(b0), "=r"(b1) : "r"(addr));
}
static __device__ __forceinline__ void mma16816(float& c0, float& c1, float& c2,
                                                float& c3, const uint32_t* a,
                                                uint32_t b0, uint32_t b1) {
    asm volatile(
        "mma.sync.aligned.m16n8k16.row.col.f32.f16.f16.f32 "
        "{%0,%1,%2,%3}, {%4,%5,%6,%7}, {%8,%9}, {%0,%1,%2,%3};"
        : "+f"(c0), "+f"(c1), "+f"(c2), "+f"(c3)
        : "r"(a[0]), "r"(a[1]), "r"(a[2]), "r"(a[3]), "r"(b0), "r"(b1));
}

// ---------------------------------------------------------------------------
// One block = one expert; warp w owns rows [w*128, w*128+128), 8 m16 chunks.
// Per chunk: convert 16 rows -> SMEM fp16 -> ldmatrix -> 8x4 mma -> in-register
// sigmoid + fc3 dot -> quad reduce -> strided write (L2 merges across experts).
// ---------------------------------------------------------------------------
__global__ __launch_bounds__(THREADS)
void golem_hmma_kernel(const float* __restrict__ noise,   // [E, B, H]
                       const float* __restrict__ W2,      // [E, H, H]
                       const float* __restrict__ b2,      // [E, H]
                       const float* __restrict__ W3,      // [E, H]
                       const float* __restrict__ b3,      // [E]
                       const float* __restrict__ T,       // [B]
                       const float* __restrict__ alpha,
                       const float* __restrict__ beta,
                       const float* __restrict__ bias,
                       float* __restrict__ out)           // [B,E] + [B]
{
    __shared__ Smem s;
    const int e   = blockIdx.x;
    const int tid = threadIdx.x;
    const int w   = tid >> 5;
    const int l   = tid & 31;

    // T_embed piggybacks on block 0
    if (e == 0) {
        float inva = __fdividef(1.0f, alpha[0]);
        float be = beta[0], bi = bias[0];
        for (int i = tid; i < NB; i += THREADS)
            out[(size_t)NB * NE + i] = inva * cosf(be * T[i] + bi);
    }

    // Stage W2[e] transposed -> Wt[o][j] fp16
    const float* W2e = W2 + (size_t)e * NH * NH;
    for (int i = tid; i < NH * NH; i += THREADS) {
        int j = i >> 6, o = i & 63;
        s.Wt[o][j] = __float2half_rn(W2e[i]);
    }
    if (tid < NH) {
        s.b2s[tid] = b2[(size_t)e * NH + tid];
        s.W3s[tid] = W3[(size_t)e * NH + tid];
    }
    __syncthreads();

    // Per-thread (b2, W3) for the 16 output columns this thread owns:
    // n-tile n -> cols o = n*8 + 2*(l&3) + {0,1}
    float pb2[16], pw3[16];
    #pragma unroll
    for (int n = 0; n < 8; n++) {
        int o = n * 8 + 2 * (l & 3);
        pb2[2 * n]     = s.b2s[o];
        pb2[2 * n + 1] = s.b2s[o + 1];
        pw3[2 * n]     = s.W3s[o];
        pw3[2 * n + 1] = s.W3s[o + 1];
    }
    const float b3e = b3[e];

    const uint32_t aBase  = smem_u32(&s.A[w][0][0]);
    const uint32_t wtBase = smem_u32(&s.Wt[0][0]);
    // A ldmatrix (m16k16 row-major): lane -> row (l&15), 16B chunk (l>>4)
    const uint32_t aLd = aBase + (uint32_t)(l & 15) * (LDA * 2) + (uint32_t)(l >> 4) * 16;
    // B ldmatrix (n8k16 from Wt rows = o): lanes 0..15 -> row (l&7), k-half ((l>>3)&1)
    const uint32_t bLd = wtBase + (uint32_t)(l & 7) * (LDA * 2) + (uint32_t)((l >> 3) & 1) * 16;
    // convert: lane l -> row l/2, halves (l&1)*32..+31
    const uint32_t cvtDst = aBase + (uint32_t)(l >> 1) * (LDA * 2) + (uint32_t)(l & 1) * 64;

    const float* nbase = noise + ((size_t)e * NB + (size_t)w * RPW) * NH;

    #pragma unroll 1
    for (int ch = 0; ch < CHUNKS; ch++) {
        __syncwarp();   // protect A tile vs previous chunk's ldmatrix
        // ---- convert 16 rows: h = sigmoid(4*noise - 2), fp16 ----
        const float4* src = (const float4*)(nbase + ((size_t)ch * 16 + (l >> 1)) * NH
                                            + (l & 1) * 32);
        #pragma unroll
        for (int i = 0; i < 4; i++) {
            float4 v0 = src[2 * i];
            float4 v1 = src[2 * i + 1];
            uint32_t p0 = sig2_h(v0.x, v0.y);
            uint32_t p1 = sig2_h(v0.z, v0.w);
            uint32_t p2 = sig2_h(v1.x, v1.y);
            uint32_t p3 = sig2_h(v1.z, v1.w);
            asm volatile("st.shared.v4.b32 [%0], {%1,%2,%3,%4};"
                         :: "r"(cvtDst + (uint32_t)i * 16),
                            "r"(p0), "r"(p1), "r"(p2), "r"(p3) : "memory");
        }
        __syncwarp();

        // ---- A fragments: 4 K-steps ----
        uint32_t a[4][4];
        #pragma unroll
        for (int ks = 0; ks < 4; ks++)
            ldsm_x4(a[ks], aLd + (uint32_t)ks * 32);

        // ---- GEMM + fused epilogue per n-tile ----
        float acc0 = 0.0f, acc1 = 0.0f;   // rows l/4 and l/4+8
        #pragma unroll
        for (int n = 0; n < 8; n++) {
            float c0 = 0.0f, c1 = 0.0f, c2 = 0.0f, c3 = 0.0f;
            #pragma unroll
            for (int ks = 0; ks < 4; ks++) {
                uint32_t b0, b1;
                ldsm_x2(b0, b1, bLd + (uint32_t)n * 8 * (LDA * 2) + (uint32_t)ks * 32);
                mma16816(c0, c1, c2, c3, a[ks], b0, b1);
            }
            acc0 += fast_sigmoid(c0 + pb2[2 * n])     * pw3[2 * n];
            acc0 += fast_sigmoid(c1 + pb2[2 * n + 1]) * pw3[2 * n + 1];
            acc1 += fast_sigmoid(c2 + pb2[2 * n])     * pw3[2 * n];
            acc1 += fast_sigmoid(c3 + pb2[2 * n + 1]) * pw3[2 * n + 1];
        }

        // quad reduce over (l&3): columns are split across the 4 quad lanes
        acc0 += __shfl_xor_sync(0xffffffffu, acc0, 1);
        acc0 += __shfl_xor_sync(0xffffffffu, acc0, 2);
        acc1 += __shfl_xor_sync(0xffffffffu, acc1, 1);
        acc1 += __shfl_xor_sync(0xffffffffu, acc1, 2);

        if ((l & 3) == 0) {
            int r = w * RPW + ch * 16 + (l >> 2);
            out[(size_t)r * NE + e]       = acc0 + b3e;
            out[(size_t)(r + 8) * NE + e] = acc1 + b3e;
        }
    }
}

// ---------------------------------------------------------------------------
// kernel_launch — inputs: 0:T 1:noise 2:W1(dead) 3:W2 4:b2 5:W3 6:b3
//                          7:alpha 8:beta 9:bias.  Output fp32: B_mat[B,E] + T_embed[B]
// ---------------------------------------------------------------------------
extern "C" void kernel_launch(void* const* d_in, const int* in_sizes, int n_in,
                              void* d_out, int out_size)
{
    const float* T     = (const float*)d_in[0];
    const float* noise = (const float*)d_in[1];
    const float* W2    = (const float*)d_in[3];
    const float* b2    = (const float*)d_in[4];
    const float* W3    = (const float*)d_in[5];
    const float* b3    = (const float*)d_in[6];
    const float* alpha = (const float*)d_in[7];
    const float* beta  = (const float*)d_in[8];
    const float* bias  = (const float*)d_in[9];

    golem_hmma_kernel<<<NE, THREADS>>>(noise, W2, b2, W3, b3,
                                       T, alpha, beta, bias, (float*)d_out);
}

// round 5
// speedup vs baseline: 2.9324x; 1.4643x over previous
#include <cuda_runtime.h>
#include <cuda_fp16.h>
#include <cstdint>

// Problem constants
#define NE       1024   // experts
#define NB       1024   // batch
#define NH       64     // hidden width
#define WARPS    8
#define THREADS  256
#define RPW      128    // rows per warp  (NB / WARPS)
#define CHUNKS   8      // m16 chunks per warp (RPW / 16)
#define LDA      72     // padded halves per SMEM row (144 B -> conflict-free ldmatrix)

struct Smem {
    __half Wt[NH][LDA];          // Wt[o][j] = W2[j][o]  (B, col-major view)
    __half A[WARPS][16][LDA];    // per-warp fp16 h tile
    float  b2s[NH];
    float  W3s[NH];
};

static __device__ __forceinline__ uint32_t smem_u32(const void* p) {
    uint32_t a;
    asm("{ .reg .u64 t; cvta.to.shared.u64 t, %1; cvt.u32.u64 %0, t; }"
        : "=r"(a) : "l"(p));
    return a;
}

static __device__ __forceinline__ float fast_sigmoid(float x) {
    return __fdividef(1.0f, 1.0f + __expf(-x));
}

// h = sigmoid(4u-2) = 0.5 + 0.5*tanh(2u-1): one MUFU.TANH per 2 elements (f16x2)
static __device__ __forceinline__ uint32_t sig2_h(float a, float b) {
    __half2 t = __floats2half2_rn(2.0f * a - 1.0f, 2.0f * b - 1.0f);
    uint32_t ti = *(uint32_t*)&t, to;
    asm("tanh.approx.f16x2 %0, %1;" : "=r"(to) : "r"(ti));
    __half2 th = *(__half2*)&to;
    __half2 hv = __hfma2(th, __half2half2(__float2half(0.5f)),
                             __half2half2(__float2half(0.5f)));
    return *(uint32_t*)&hv;
}

static __device__ __forceinline__ void ldsm_x4(uint32_t* r, uint32_t addr) {
    asm volatile("ldmatrix.sync.aligned.m8n8.x4.shared.b16 {%0,%1,%2,%3}, [%4];"
                 : "=r"(r[0]), "=r"(r[1]), "=r"(r[2]), "=r"(r[3]) : "r"(addr));
}
static __device__ __forceinline__ void ldsm_x2(uint32_t& b0, uint32_t& b1,
                                               uint32_t addr) {
    asm volatile("ldmatrix.sync.aligned.m8n8.x2.shared.b16 {%0,%1}, [%2];"
                 : "=r"(b0), "=r"(b1) : "r"(addr));
}
static __device__ __forceinline__ void mma16816(float& c0, float& c1, float& c2,
                                                float& c3, const uint32_t* a,
                                                uint32_t b0, uint32_t b1) {
    asm volatile(
        "mma.sync.aligned.m16n8k16.row.col.f32.f16.f16.f32 "
        "{%0,%1,%2,%3}, {%4,%5,%6,%7}, {%8,%9}, {%0,%1,%2,%3};"
        : "+f"(c0), "+f"(c1), "+f"(c2), "+f"(c3)
        : "r"(a[0]), "r"(a[1]), "r"(a[2]), "r"(a[3]), "r"(b0), "r"(b1));
}

// ---------------------------------------------------------------------------
// One block = one expert; warp w owns rows [w*128, w*128+128), 8 m16 chunks.
// B fragments (W2^T) are hoisted into registers ONCE per expert; per chunk:
// convert 16 rows -> SMEM fp16 -> 4x ldmatrix.x4 (A) -> 32 mma -> in-register
// sigmoid + fc3 dot -> quad shfl reduce -> strided write (L2 merges experts).
// ---------------------------------------------------------------------------
__global__ __launch_bounds__(THREADS, 2)
void golem_hmma_kernel(const float* __restrict__ noise,   // [E, B, H]
                       const float* __restrict__ W2,      // [E, H, H]
                       const float* __restrict__ b2,      // [E, H]
                       const float* __restrict__ W3,      // [E, H]
                       const float* __restrict__ b3,      // [E]
                       const float* __restrict__ T,       // [B]
                       const float* __restrict__ alpha,
                       const float* __restrict__ beta,
                       const float* __restrict__ bias,
                       float* __restrict__ out)           // [B,E] + [B]
{
    __shared__ Smem s;
    const int e   = blockIdx.x;
    const int tid = threadIdx.x;
    const int w   = tid >> 5;
    const int l   = tid & 31;

    // T_embed piggybacks on block 0
    if (e == 0) {
        float inva = __fdividef(1.0f, alpha[0]);
        float be = beta[0], bi = bias[0];
        for (int i = tid; i < NB; i += THREADS)
            out[(size_t)NB * NE + i] = inva * cosf(be * T[i] + bi);
    }

    // Stage W2[e] transposed -> Wt[o][j] fp16
    const float* W2e = W2 + (size_t)e * NH * NH;
    for (int i = tid; i < NH * NH; i += THREADS) {
        int j = i >> 6, o = i & 63;
        s.Wt[o][j] = __float2half_rn(W2e[i]);
    }
    if (tid < NH) {
        s.b2s[tid] = b2[(size_t)e * NH + tid];
        s.W3s[tid] = W3[(size_t)e * NH + tid];
    }
    __syncthreads();

    // Per-thread epilogue constants for cols o = n*8 + 2*(l&3) + {0,1}:
    // W3 fp32 (multiplies output), b2 packed half2 (only biases sigmoid input).
    float   pw3[16];
    __half2 pb2h[8];
    #pragma unroll
    for (int n = 0; n < 8; n++) {
        int o = n * 8 + 2 * (l & 3);
        pw3[2 * n]     = s.W3s[o];
        pw3[2 * n + 1] = s.W3s[o + 1];
        pb2h[n] = __floats2half2_rn(s.b2s[o], s.b2s[o + 1]);
    }
    const float b3e = b3[e];

    const uint32_t aBase  = smem_u32(&s.A[w][0][0]);
    const uint32_t wtBase = smem_u32(&s.Wt[0][0]);
    // A ldmatrix (m16k16 row-major): lane -> row (l&15), 16B chunk (l>>4)
    const uint32_t aLd = aBase + (uint32_t)(l & 15) * (LDA * 2) + (uint32_t)(l >> 4) * 16;
    // B ldmatrix (n8k16 from Wt rows = o): lanes 0..15 -> row (l&7), k-half ((l>>3)&1)
    const uint32_t bLd = wtBase + (uint32_t)(l & 7) * (LDA * 2) + (uint32_t)((l >> 3) & 1) * 16;
    // convert: lane l -> row l/2, halves (l&1)*32..+31
    const uint32_t cvtDst = aBase + (uint32_t)(l >> 1) * (LDA * 2) + (uint32_t)(l & 1) * 64;

    // ---- hoist B fragments: constant per expert, loaded once ----
    uint32_t bf[8][4][2];
    #pragma unroll
    for (int n = 0; n < 8; n++)
        #pragma unroll
        for (int ks = 0; ks < 4; ks++)
            ldsm_x2(bf[n][ks][0], bf[n][ks][1],
                    bLd + (uint32_t)n * 8 * (LDA * 2) + (uint32_t)ks * 32);

    const float* nbase = noise + ((size_t)e * NB + (size_t)w * RPW) * NH;

    #pragma unroll 1
    for (int ch = 0; ch < CHUNKS; ch++) {
        __syncwarp();   // protect A tile vs previous chunk's ldmatrix
        // ---- convert 16 rows: h = sigmoid(4*noise - 2), fp16 ----
        const float4* src = (const float4*)(nbase + ((size_t)ch * 16 + (l >> 1)) * NH
                                            + (l & 1) * 32);
        #pragma unroll
        for (int i = 0; i < 4; i++) {
            float4 v0 = src[2 * i];
            float4 v1 = src[2 * i + 1];
            uint32_t p0 = sig2_h(v0.x, v0.y);
            uint32_t p1 = sig2_h(v0.z, v0.w);
            uint32_t p2 = sig2_h(v1.x, v1.y);
            uint32_t p3 = sig2_h(v1.z, v1.w);
            asm volatile("st.shared.v4.b32 [%0], {%1,%2,%3,%4};"
                         :: "r"(cvtDst + (uint32_t)i * 16),
                            "r"(p0), "r"(p1), "r"(p2), "r"(p3) : "memory");
        }
        __syncwarp();

        // ---- A fragments: 4 K-steps ----
        uint32_t a[4][4];
        #pragma unroll
        for (int ks = 0; ks < 4; ks++)
            ldsm_x4(a[ks], aLd + (uint32_t)ks * 32);

        // ---- GEMM + fused epilogue per n-tile (B from registers) ----
        float acc0 = 0.0f, acc1 = 0.0f;   // rows l/4 and l/4+8
        #pragma unroll
        for (int n = 0; n < 8; n++) {
            float2 b2p = __half22float2(pb2h[n]);
            float c0 = b2p.x, c1 = b2p.y, c2 = b2p.x, c3 = b2p.y;
            #pragma unroll
            for (int ks = 0; ks < 4; ks++)
                mma16816(c0, c1, c2, c3, a[ks], bf[n][ks][0], bf[n][ks][1]);
            acc0 += fast_sigmoid(c0) * pw3[2 * n];
            acc0 += fast_sigmoid(c1) * pw3[2 * n + 1];
            acc1 += fast_sigmoid(c2) * pw3[2 * n];
            acc1 += fast_sigmoid(c3) * pw3[2 * n + 1];
        }

        // quad reduce over (l&3): columns are split across the 4 quad lanes
        acc0 += __shfl_xor_sync(0xffffffffu, acc0, 1);
        acc0 += __shfl_xor_sync(0xffffffffu, acc0, 2);
        acc1 += __shfl_xor_sync(0xffffffffu, acc1, 1);
        acc1 += __shfl_xor_sync(0xffffffffu, acc1, 2);

        if ((l & 3) == 0) {
            int r = w * RPW + ch * 16 + (l >> 2);
            out[(size_t)r * NE + e]       = acc0 + b3e;
            out[(size_t)(r + 8) * NE + e] = acc1 + b3e;
        }
    }
}

// ---------------------------------------------------------------------------
// kernel_launch — inputs: 0:T 1:noise 2:W1(dead) 3:W2 4:b2 5:W3 6:b3
//                          7:alpha 8:beta 9:bias.  Output fp32: B_mat[B,E] + T_embed[B]
// ---------------------------------------------------------------------------
extern "C" void kernel_launch(void* const* d_in, const int* in_sizes, int n_in,
                              void* d_out, int out_size)
{
    const float* T     = (const float*)d_in[0];
    const float* noise = (const float*)d_in[1];
    const float* W2    = (const float*)d_in[3];
    const float* b2    = (const float*)d_in[4];
    const float* W3    = (const float*)d_in[5];
    const float* b3    = (const float*)d_in[6];
    const float* alpha = (const float*)d_in[7];
    const float* beta  = (const float*)d_in[8];
    const float* bias  = (const float*)d_in[9];

    golem_hmma_kernel<<<NE, THREADS>>>(noise, W2, b2, W3, b3,
                                       T, alpha, beta, bias, (float*)d_out);
}